// round 11
// baseline (speedup 1.0000x reference)
#include <cuda_runtime.h>

#define NMAX 50000
#define EMAX 800000
#define HD   64
#define FIN  128
#define NHEADS 4

// ---------------- scratch (static device memory; no allocs) ----------------
__device__ __align__(16) float d_h   [NMAX * HD];          // dinv-scaled xW1 (gather src)
__device__ __align__(16) float d_h2  [NMAX * HD];          // GCN accumulator
__device__ __align__(16) float d_hg  [NMAX * NHEADS * HD]; // GAT features [N,4,64]
__device__ __align__(16) float d_asrc[NMAX * NHEADS];
__device__ __align__(16) float d_adst[NMAX * NHEADS];
__device__ __align__(16) float d_den [NMAX * NHEADS];      // softmax denom -> 0.25/denom
__device__ __align__(16) float d_alpha[EMAX * NHEADS];     // per-edge exp values
__device__ __align__(16) float d_hga [NMAX * HD];          // GAT aggregation
__device__ __align__(16) float d_mean[NMAX * HD];          // SAGE sum accumulator
__device__ float d_cnt [NMAX];                             // in-degree (no self loops)
__device__ float d_dinv[NMAX];                             // rsqrt(deg+1)
__device__ int   d_row32[EMAX];
__device__ int   d_col32[EMAX];

// ---------------- helpers ----------------
__device__ __forceinline__ float lrelu(float x) { return x > 0.f ? x : 0.2f * x; }

__device__ __forceinline__ void red_add_v4(float4* p, float4 v) {
    asm volatile("red.global.add.v4.f32 [%0], {%1, %2, %3, %4};"
                 :: "l"(p), "f"(v.x), "f"(v.y), "f"(v.z), "f"(v.w) : "memory");
}

// ---------------- small kernels ----------------

__global__ void k_zero(int n) {
    int total = n * (HD / 4);
    int i = blockIdx.x * blockDim.x + threadIdx.x;
    if (i < total) reinterpret_cast<float4*>(d_mean)[i] = make_float4(0.f, 0.f, 0.f, 0.f);
    if (i < n) d_cnt[i] = 0.f;
}

// edge_index is INT32 (JAX x64 disabled). Copy + validate + in-degree count.
__global__ void k_edges32(const int* __restrict__ row0,
                          const int* __restrict__ col0, int e, int n) {
    int i = blockIdx.x * blockDim.x + threadIdx.x;
    if (i < e) {
        int r = row0[i];
        int c = col0[i];
        if ((unsigned)r >= (unsigned)n) r = 0;
        if ((unsigned)c >= (unsigned)n) c = 0;
        d_row32[i] = r;
        d_col32[i] = c;
        atomicAdd(&d_cnt[c], 1.f);
    }
}

__global__ void k_dinv(int n) {
    int i = blockIdx.x * blockDim.x + threadIdx.x;
    if (i < n) d_dinv[i] = rsqrtf(d_cnt[i] + 1.0f);
}

// ---------------- GCN GEMM (smem W + padded smem x, 2x8 tile) ----------------
// v = dinv[row]*(x@W1); d_h = v; d_h2 = v.  64 rows/block, 256 threads.
// dyn smem: Ws[128][64] (32KB) + xs[64][132] (33.8KB)
#define GCN_XSTR 132
#define GCN_SMEM ((FIN * HD + 64 * GCN_XSTR) * 4)
__global__ void __launch_bounds__(256) k_gemm_gcn(const float* __restrict__ A,
                                                  const float* __restrict__ W, int n) {
    extern __shared__ float sm[];
    float* Ws = sm;                    // [128][64] natural layout
    float* xs = sm + FIN * HD;         // [64][132] padded
    int tid = threadIdx.x;
    for (int i4 = tid; i4 < FIN * HD / 4; i4 += 256)
        reinterpret_cast<float4*>(Ws)[i4] = __ldg(reinterpret_cast<const float4*>(W) + i4);
    long long base = (long long)blockIdx.x * 64;
    for (int i4 = tid; i4 < 64 * (FIN / 4); i4 += 256) {
        int row = i4 >> 5;
        int col4 = i4 & 31;
        float4 v = make_float4(0.f, 0.f, 0.f, 0.f);
        if (base + row < n)
            v = __ldg(reinterpret_cast<const float4*>(A + (base + row) * FIN) + col4);
        float* dst = xs + row * GCN_XSTR + col4 * 4;
        dst[0] = v.x; dst[1] = v.y; dst[2] = v.z; dst[3] = v.w;
    }
    __syncthreads();
    int j0 = tid & 7;          // 8 col-groups of 8
    int sg = tid >> 3;         // 0..31 -> rows sg*2, sg*2+1
    const float* x0p = xs + (sg * 2) * GCN_XSTR;
    const float* x1p = xs + (sg * 2 + 1) * GCN_XSTR;
    float4 a00 = make_float4(0.f, 0.f, 0.f, 0.f), a01 = a00, a10 = a00, a11 = a00;
#pragma unroll 4
    for (int k = 0; k < FIN; k++) {
        float4 w0 = reinterpret_cast<const float4*>(Ws + k * HD)[j0 * 2];
        float4 w1 = reinterpret_cast<const float4*>(Ws + k * HD)[j0 * 2 + 1];
        float x0 = x0p[k], x1 = x1p[k];
        a00.x += x0 * w0.x; a00.y += x0 * w0.y; a00.z += x0 * w0.z; a00.w += x0 * w0.w;
        a01.x += x0 * w1.x; a01.y += x0 * w1.y; a01.z += x0 * w1.z; a01.w += x0 * w1.w;
        a10.x += x1 * w0.x; a10.y += x1 * w0.y; a10.z += x1 * w0.z; a10.w += x1 * w0.w;
        a11.x += x1 * w1.x; a11.y += x1 * w1.y; a11.z += x1 * w1.z; a11.w += x1 * w1.w;
    }
    long long r0 = base + sg * 2, r1 = r0 + 1;
    if (r0 < n) {
        float dv = __ldg(&d_dinv[r0]);
        float4 v0 = make_float4(a00.x * dv, a00.y * dv, a00.z * dv, a00.w * dv);
        float4 v1 = make_float4(a01.x * dv, a01.y * dv, a01.z * dv, a01.w * dv);
        reinterpret_cast<float4*>(d_h)[r0 * 16 + j0 * 2]      = v0;
        reinterpret_cast<float4*>(d_h)[r0 * 16 + j0 * 2 + 1]  = v1;
        reinterpret_cast<float4*>(d_h2)[r0 * 16 + j0 * 2]     = v0;
        reinterpret_cast<float4*>(d_h2)[r0 * 16 + j0 * 2 + 1] = v1;
    }
    if (r1 < n) {
        float dv = __ldg(&d_dinv[r1]);
        float4 v0 = make_float4(a10.x * dv, a10.y * dv, a10.z * dv, a10.w * dv);
        float4 v1 = make_float4(a11.x * dv, a11.y * dv, a11.z * dv, a11.w * dv);
        reinterpret_cast<float4*>(d_h)[r1 * 16 + j0 * 2]      = v0;
        reinterpret_cast<float4*>(d_h)[r1 * 16 + j0 * 2 + 1]  = v1;
        reinterpret_cast<float4*>(d_h2)[r1 * 16 + j0 * 2]     = v0;
        reinterpret_cast<float4*>(d_h2)[r1 * 16 + j0 * 2 + 1] = v1;
    }
}

// ---------------- GAT GEMM (smem W swizzled + smem x, 8x8 tile) ----------------
// xs = relu(dinv*h2 + b1); d_hg = xs @ Wg.  64 rows/block, 256 threads.
// dyn smem: Ws 64x256 swizzled (64KB) + xs[64][64] (16KB)
#define GAT_SMEM ((HD * NHEADS * HD + 64 * HD) * 4)
__global__ void __launch_bounds__(256) k_gemm_gat(const float* __restrict__ Wg,
                                                  const float* __restrict__ b1, int n) {
    extern __shared__ float sm[];
    float* Ws = sm;                    // [64][2][32] float4-swizzled
    float* xs = sm + HD * NHEADS * HD; // [64][64]
    const int M = NHEADS * HD;         // 256
    int tid = threadIdx.x;
    // load W swizzled: src float4 g = k*64 + c4  ->  dst k*64 + (c4&1)*32 + (c4>>1)
    for (int g = tid; g < HD * M / 4; g += 256) {
        int k = g >> 6, c4 = g & 63;
        reinterpret_cast<float4*>(Ws)[(k << 6) + ((c4 & 1) << 5) + (c4 >> 1)] =
            __ldg(reinterpret_cast<const float4*>(Wg) + g);
    }
    long long base = (long long)blockIdx.x * 64;
    for (int i4 = tid; i4 < 64 * (HD / 4); i4 += 256) {
        int row = i4 >> 4;
        int col4 = i4 & 15;
        float4 v = make_float4(0.f, 0.f, 0.f, 0.f);
        if (base + row < n) {
            float4 h2v = __ldg(reinterpret_cast<const float4*>(d_h2) + (base + row) * 16 + col4);
            float4 bv  = __ldg(reinterpret_cast<const float4*>(b1) + col4);
            float dv = __ldg(&d_dinv[base + row]);
            v.x = fmaxf(dv * h2v.x + bv.x, 0.f);
            v.y = fmaxf(dv * h2v.y + bv.y, 0.f);
            v.z = fmaxf(dv * h2v.z + bv.z, 0.f);
            v.w = fmaxf(dv * h2v.w + bv.w, 0.f);
        }
        reinterpret_cast<float4*>(xs)[i4] = v;
    }
    __syncthreads();
    int j0 = tid & 31;         // 32 col-groups of 8
    int sg = tid >> 5;         // warp id: rows sg*8 .. sg*8+7
    float4 acc[8][2];
#pragma unroll
    for (int r = 0; r < 8; r++) {
        acc[r][0] = make_float4(0.f, 0.f, 0.f, 0.f);
        acc[r][1] = make_float4(0.f, 0.f, 0.f, 0.f);
    }
    const float* xrow = xs + sg * 8 * HD;
#pragma unroll 2
    for (int k = 0; k < HD; k++) {
        float4 w0 = reinterpret_cast<const float4*>(Ws)[(k << 6) + j0];        // lo half
        float4 w1 = reinterpret_cast<const float4*>(Ws)[(k << 6) + 32 + j0];   // hi half
#pragma unroll
        for (int r = 0; r < 8; r++) {
            float xv = xrow[r * HD + k];
            acc[r][0].x += xv * w0.x; acc[r][0].y += xv * w0.y;
            acc[r][0].z += xv * w0.z; acc[r][0].w += xv * w0.w;
            acc[r][1].x += xv * w1.x; acc[r][1].y += xv * w1.y;
            acc[r][1].z += xv * w1.z; acc[r][1].w += xv * w1.w;
        }
    }
#pragma unroll
    for (int r = 0; r < 8; r++) {
        long long row = base + sg * 8 + r;
        if (row < n) {
            reinterpret_cast<float4*>(d_hg)[row * 64 + j0 * 2]     = acc[r][0];
            reinterpret_cast<float4*>(d_hg)[row * 64 + j0 * 2 + 1] = acc[r][1];
        }
    }
}

// ---------------- scatters / attention ----------------

// GCN scatter (float4): h2[c] += h[r]
__global__ void k_gcn_scatter(int e) {
    int total = e * (HD / 4);
    int t = blockIdx.x * blockDim.x + threadIdx.x;
    if (t < total) {
        int ed = t >> 4, q = t & 15;
        int r = __ldg(&d_row32[ed]);
        int c = __ldg(&d_col32[ed]);
        float4 v = reinterpret_cast<const float4*>(d_h)[r * 16 + q];
        red_add_v4(&reinterpret_cast<float4*>(d_h2)[c * 16 + q], v);
    }
}

// per-(node,head) attention logits + denom init = exp(self logit)
__global__ void k_att(const float* __restrict__ att_src,
                      const float* __restrict__ att_dst, int n) {
    long long w = (long long)(blockIdx.x * blockDim.x + threadIdx.x) >> 5;
    int lane = threadIdx.x & 31;
    long long total = (long long)n * NHEADS;
    long long stride = ((long long)gridDim.x * blockDim.x) >> 5;
    for (; w < total; w += stride) {
        int node = (int)(w >> 2), head = (int)(w & 3);
        const float* hgp = &d_hg[(long long)node * (NHEADS * HD) + head * HD];
        float s = hgp[lane] * __ldg(&att_src[head * HD + lane]) +
                  hgp[lane + 32] * __ldg(&att_src[head * HD + lane + 32]);
        float t = hgp[lane] * __ldg(&att_dst[head * HD + lane]) +
                  hgp[lane + 32] * __ldg(&att_dst[head * HD + lane + 32]);
#pragma unroll
        for (int o = 16; o; o >>= 1) {
            s += __shfl_down_sync(0xffffffffu, s, o);
            t += __shfl_down_sync(0xffffffffu, t, o);
        }
        if (lane == 0) {
            d_asrc[w] = s;
            d_adst[w] = t;
            d_den[w]  = expf(lrelu(s + t));
        }
    }
}

// per-edge ex = exp(lrelu(asrc[r]+adst[c])): store + vector-RED into denom
__global__ void k_den_edges(int e) {
    int i = blockIdx.x * blockDim.x + threadIdx.x;
    if (i < e) {
        int r = d_row32[i], c = d_col32[i];
        const float4 as = reinterpret_cast<const float4*>(d_asrc)[r];
        const float4 ad = reinterpret_cast<const float4*>(d_adst)[c];
        float4 ex;
        ex.x = expf(lrelu(as.x + ad.x));
        ex.y = expf(lrelu(as.y + ad.y));
        ex.z = expf(lrelu(as.z + ad.z));
        ex.w = expf(lrelu(as.w + ad.w));
        reinterpret_cast<float4*>(d_alpha)[i] = ex;
        red_add_v4(&reinterpret_cast<float4*>(d_den)[c], ex);
    }
}

// hga init (float4): self contribution; also invert denom in place (0.25/den)
__global__ void k_hga_init(int n) {
    int total = n * (HD / 4);
    int t = blockIdx.x * blockDim.x + threadIdx.x;
    if (t < total) {
        int node = t >> 4, q = t & 15;
        const float4 as = reinterpret_cast<const float4*>(d_asrc)[node];
        const float4 ad = reinterpret_cast<const float4*>(d_adst)[node];
        const float4 dn = reinterpret_cast<const float4*>(d_den)[node];
        float4 inv = make_float4(0.25f / dn.x, 0.25f / dn.y, 0.25f / dn.z, 0.25f / dn.w);
        if (q == 0) reinterpret_cast<float4*>(d_den)[node] = inv;
        float wx = expf(lrelu(as.x + ad.x)) * inv.x;
        float wy = expf(lrelu(as.y + ad.y)) * inv.y;
        float wz = expf(lrelu(as.z + ad.z)) * inv.z;
        float ww = expf(lrelu(as.w + ad.w)) * inv.w;
        const float4* hg4 = reinterpret_cast<const float4*>(d_hg);
        long long base = (long long)node * 64;
        float4 a = hg4[base + 0 * 16 + q];
        float4 b = hg4[base + 1 * 16 + q];
        float4 cc = hg4[base + 2 * 16 + q];
        float4 dd = hg4[base + 3 * 16 + q];
        float4 s;
        s.x = wx * a.x + wy * b.x + wz * cc.x + ww * dd.x;
        s.y = wx * a.y + wy * b.y + wz * cc.y + ww * dd.y;
        s.z = wx * a.z + wy * b.z + wz * cc.z + ww * dd.z;
        s.w = wx * a.w + wy * b.w + wz * cc.w + ww * dd.w;
        reinterpret_cast<float4*>(d_hga)[node * 16 + q] = s;
    }
}

// GAT scatter (float4)
__global__ void k_gat_scatter(int e) {
    int total = e * (HD / 4);
    int t = blockIdx.x * blockDim.x + threadIdx.x;
    if (t < total) {
        int ed = t >> 4, q = t & 15;
        int r = __ldg(&d_row32[ed]);
        int c = __ldg(&d_col32[ed]);
        const float4 ex = reinterpret_cast<const float4*>(d_alpha)[ed];
        const float4 dn = reinterpret_cast<const float4*>(d_den)[c];   // 0.25/den
        float wx = ex.x * dn.x, wy = ex.y * dn.y, wz = ex.z * dn.z, ww = ex.w * dn.w;
        const float4* hg4 = reinterpret_cast<const float4*>(d_hg);
        long long base = (long long)r * 64;
        float4 a = hg4[base + 0 * 16 + q];
        float4 b = hg4[base + 1 * 16 + q];
        float4 cc = hg4[base + 2 * 16 + q];
        float4 dd = hg4[base + 3 * 16 + q];
        float4 s;
        s.x = wx * a.x + wy * b.x + wz * cc.x + ww * dd.x;
        s.y = wx * a.y + wy * b.y + wz * cc.y + ww * dd.y;
        s.z = wx * a.z + wy * b.z + wz * cc.z + ww * dd.z;
        s.w = wx * a.w + wy * b.w + wz * cc.w + ww * dd.w;
        red_add_v4(&reinterpret_cast<float4*>(d_hga)[c * 16 + q], s);
    }
}

// SAGE scatter (float4): mean[c] += relu(hga[r] + bg)   (h3 computed on the fly)
__global__ void k_sage_scatter(const float* __restrict__ bg, int e) {
    int total = e * (HD / 4);
    int t = blockIdx.x * blockDim.x + threadIdx.x;
    if (t < total) {
        int ed = t >> 4, q = t & 15;
        int r = __ldg(&d_row32[ed]);
        int c = __ldg(&d_col32[ed]);
        float4 h = reinterpret_cast<const float4*>(d_hga)[r * 16 + q];
        float4 bv = __ldg(reinterpret_cast<const float4*>(bg) + q);
        float4 v;
        v.x = fmaxf(h.x + bv.x, 0.f);
        v.y = fmaxf(h.y + bv.y, 0.f);
        v.z = fmaxf(h.z + bv.z, 0.f);
        v.w = fmaxf(h.w + bv.w, 0.f);
        red_add_v4(&reinterpret_cast<float4*>(d_mean)[c * 16 + q], v);
    }
}

// final: emb = mean@Wl + bl + relu(hga+bg)@Wr ; MLP heads ; outputs
__global__ void k_final(const float* __restrict__ Wl, const float* __restrict__ bl,
                        const float* __restrict__ Wr, const float* __restrict__ bg,
                        const float* __restrict__ a1w, const float* __restrict__ a1b,
                        const float* __restrict__ a2w, const float* __restrict__ a2b,
                        const float* __restrict__ r1w, const float* __restrict__ r1b,
                        const float* __restrict__ r2w, const float* __restrict__ r2b,
                        float* __restrict__ out_emb, float* __restrict__ out_an,
                        float* __restrict__ out_risk, int n) {
    __shared__ float Wls[HD * HD], Wrs[HD * HD];
    __shared__ float ms[4][HD], hs[4][HD], embs[4][HD];
    int tid = threadIdx.x;
    for (int i = tid; i < HD * HD; i += blockDim.x) {
        Wls[i] = Wl[i];
        Wrs[i] = Wr[i];
    }
    int sub = tid >> 6, j = tid & 63;
    int lane = tid & 31, wp = tid >> 5;
    int nd = wp >> 1, hd = wp & 1;
    for (long long base = (long long)blockIdx.x * 4; base < n;
         base += (long long)gridDim.x * 4) {
        int node = (int)base + sub;
        __syncthreads();
        if (node < n) {
            float inv = 1.f / fmaxf(d_cnt[node], 1.f);
            ms[sub][j] = d_mean[node * HD + j] * inv;
            hs[sub][j] = fmaxf(d_hga[node * HD + j] + bg[j], 0.f);
        }
        __syncthreads();
        if (node < n) {
            float acc = bl[j];
#pragma unroll 16
            for (int k = 0; k < HD; k++)
                acc += ms[sub][k] * Wls[k * HD + j] + hs[sub][k] * Wrs[k * HD + j];
            embs[sub][j] = acc;
            out_emb[(long long)node * HD + j] = acc;
        }
        __syncthreads();
        int node2 = (int)base + nd;
        if (node2 < n) {
            const float* W1p = hd ? r1w : a1w;
            float acc = hd ? __ldg(&r1b[lane]) : __ldg(&a1b[lane]);
#pragma unroll 16
            for (int k = 0; k < HD; k++)
                acc += embs[nd][k] * __ldg(&W1p[k * 32 + lane]);
            acc = fmaxf(acc, 0.f) * (hd ? __ldg(&r2w[lane]) : __ldg(&a2w[lane]));
#pragma unroll
            for (int o = 16; o; o >>= 1) acc += __shfl_down_sync(0xffffffffu, acc, o);
            if (lane == 0) {
                float b2 = hd ? __ldg(&r2b[0]) : __ldg(&a2b[0]);
                float v = 1.f / (1.f + expf(-(acc + b2)));
                if (hd) out_risk[node2] = v;
                else    out_an[node2] = v;
            }
        }
    }
}

// ---------------- launcher ----------------
extern "C" void kernel_launch(void* const* d_in, const int* in_sizes, int n_in,
                              void* d_out, int out_size) {
    const float* x   = (const float*)d_in[0];
    const int*   ei  = (const int*)d_in[1];   // int32 (JAX x64 disabled)
    const float* W1  = (const float*)d_in[2];
    const float* b1  = (const float*)d_in[3];
    const float* Wg  = (const float*)d_in[4];
    const float* ats = (const float*)d_in[5];
    const float* atd = (const float*)d_in[6];
    const float* bg  = (const float*)d_in[7];
    const float* Wl  = (const float*)d_in[8];
    const float* bl  = (const float*)d_in[9];
    const float* Wr  = (const float*)d_in[10];
    const float* a1w = (const float*)d_in[11];
    const float* a1b = (const float*)d_in[12];
    const float* a2w = (const float*)d_in[13];
    const float* a2b = (const float*)d_in[14];
    const float* r1w = (const float*)d_in[15];
    const float* r1b = (const float*)d_in[16];
    const float* r2w = (const float*)d_in[17];
    const float* r2b = (const float*)d_in[18];

    int n = in_sizes[0] / FIN;
    int e = in_sizes[1] / 2;
    const int* row0 = ei;
    const int* col0 = ei + e;

    float* out      = (float*)d_out;
    float* out_emb  = out;
    float* out_an   = out + (long long)n * HD;
    float* out_risk = out_an + n;

    static bool attr_done = false;
    if (!attr_done) {
        cudaFuncSetAttribute(k_gemm_gcn, cudaFuncAttributeMaxDynamicSharedMemorySize, GCN_SMEM);
        cudaFuncSetAttribute(k_gemm_gat, cudaFuncAttributeMaxDynamicSharedMemorySize, GAT_SMEM);
        attr_done = true;
    }

    const int B = 256;
    int gN  = (n + B - 1) / B;
    int gE  = (e + B - 1) / B;
    int gE4 = (e * (HD / 4) + B - 1) / B;
    int gN4 = (n * (HD / 4) + B - 1) / B;

    // preprocessing
    k_zero<<<gN4, B>>>(n);
    k_edges32<<<gE, B>>>(row0, col0, e, n);
    k_dinv<<<gN, B>>>(n);

    // GCN
    k_gemm_gcn<<<(n + 63) / 64, 256, GCN_SMEM>>>(x, W1, n);
    k_gcn_scatter<<<gE4, B>>>(e);

    // GAT
    k_gemm_gat<<<(n + 63) / 64, 256, GAT_SMEM>>>(Wg, b1, n);
    k_att<<<(n * NHEADS * 32 + B - 1) / B, B>>>(ats, atd, n);
    k_den_edges<<<gE, B>>>(e);
    k_hga_init<<<gN4, B>>>(n);
    k_gat_scatter<<<gE4, B>>>(e);

    // SAGE (relu+bg fused into gather)
    k_sage_scatter<<<gE4, B>>>(bg, e);

    // emb + heads
    k_final<<<(n + 3) / 4, B>>>(Wl, bl, Wr, bg, a1w, a1b, a2w, a2b,
                                r1w, r1b, r2w, r2b,
                                out_emb, out_an, out_risk, n);
}

// round 12
// speedup vs baseline: 1.0841x; 1.0841x over previous
#include <cuda_runtime.h>

#define NMAX 50000
#define EMAX 800000
#define HD   64
#define FIN  128
#define NHEADS 4

// ---------------- scratch (static device memory; no allocs) ----------------
__device__ __align__(16) float d_h   [NMAX * HD];          // dinv-scaled xW1 (gather src)
__device__ __align__(16) float d_h2  [NMAX * HD];          // GCN gather result
__device__ __align__(16) float d_hg  [NMAX * NHEADS * HD]; // GAT features [N,4,64]
__device__ __align__(16) float d_asrc[NMAX * NHEADS];
__device__ __align__(16) float d_adst[NMAX * NHEADS];
__device__ __align__(16) float d_den [NMAX * NHEADS];      // softmax denom (raw sums)
__device__ __align__(16) float d_alpha[EMAX * NHEADS];     // per-edge exp values
__device__ __align__(16) float d_hga [NMAX * HD];          // GAT aggregation
__device__ __align__(16) float d_mean[NMAX * HD];          // SAGE sums
__device__ float d_dinv[NMAX];                             // rsqrt(deg+1)
__device__ int   d_deg [NMAX];                             // in-degree (no self loops)
__device__ int   d_off [NMAX + 1];                         // CSR offsets
__device__ int   d_pos [NMAX];                             // fill cursors
__device__ int2  d_epack[EMAX];                            // CSR entries {src, edge id}
__device__ int   d_row32[EMAX];
__device__ int   d_col32[EMAX];

// ---------------- helpers ----------------
__device__ __forceinline__ float lrelu(float x) { return x > 0.f ? x : 0.2f * x; }

__device__ __forceinline__ void red_add_v4(float4* p, float4 v) {
    asm volatile("red.global.add.v4.f32 [%0], {%1, %2, %3, %4};"
                 :: "l"(p), "f"(v.x), "f"(v.y), "f"(v.z), "f"(v.w) : "memory");
}

// ---------------- CSR construction ----------------

__global__ void k_zero0(int n) {
    int i = blockIdx.x * blockDim.x + threadIdx.x;
    if (i < n) { d_deg[i] = 0; d_pos[i] = 0; }
}

// edge_index is INT32 (JAX x64 disabled). Copy + validate + in-degree count.
__global__ void k_edges32(const int* __restrict__ row0,
                          const int* __restrict__ col0, int e, int n) {
    int i = blockIdx.x * blockDim.x + threadIdx.x;
    if (i < e) {
        int r = row0[i];
        int c = col0[i];
        if ((unsigned)r >= (unsigned)n) r = 0;
        if ((unsigned)c >= (unsigned)n) c = 0;
        d_row32[i] = r;
        d_col32[i] = c;
        atomicAdd(&d_deg[c], 1);
    }
}

// single-block exclusive scan of d_deg -> d_off (n up to NMAX)
__global__ void __launch_bounds__(1024) k_scan(int n) {
    __shared__ int ss[1024];
    int tid = threadIdx.x;
    int per = (n + 1023) >> 10;
    int start = tid * per;
    int end = min(start + per, n);
    int s = 0;
    for (int i = start; i < end; i++) s += d_deg[i];
    ss[tid] = s;
    __syncthreads();
    for (int off = 1; off < 1024; off <<= 1) {
        int v = (tid >= off) ? ss[tid - off] : 0;
        __syncthreads();
        ss[tid] += v;
        __syncthreads();
    }
    int run = (tid == 0) ? 0 : ss[tid - 1];
    for (int i = start; i < end; i++) {
        d_off[i] = run;
        run += d_deg[i];
    }
    if (tid == 1023) d_off[n] = run;
}

__global__ void k_fill(int e) {
    int i = blockIdx.x * blockDim.x + threadIdx.x;
    if (i < e) {
        int r = d_row32[i], c = d_col32[i];
        int slot = atomicAdd(&d_pos[c], 1);
        d_epack[d_off[c] + slot] = make_int2(r, i);
    }
}

__global__ void k_dinv(int n) {
    int i = blockIdx.x * blockDim.x + threadIdx.x;
    if (i < n) d_dinv[i] = rsqrtf((float)d_deg[i] + 1.0f);
}

// ---------------- GCN GEMM (R10 shape): d_h = dinv[row]*(x@W1) ----------------
__global__ void k_gemm_gcn(const float* __restrict__ A, const float* __restrict__ W, int n) {
    const int K = FIN, JT = 16, SG = 16, RPT = 4;
    const int ROWS = SG * RPT;                       // 64
    __shared__ float xs[ROWS][K];
    int tid = threadIdx.x;
    int j0  = tid % JT;
    int sg  = tid / JT;
    long long base = (long long)blockIdx.x * ROWS;
    {
        const int T4 = ROWS * (K / 4);
        for (int i4 = tid; i4 < T4; i4 += 256) {
            long long row = base + i4 / (K / 4);
            int col4 = i4 % (K / 4);
            reinterpret_cast<float4*>(xs)[i4] =
                (row < n) ? __ldg(reinterpret_cast<const float4*>(A + row * K) + col4)
                          : make_float4(0.f, 0.f, 0.f, 0.f);
        }
    }
    __syncthreads();
    float4 acc[RPT];
#pragma unroll
    for (int r = 0; r < RPT; r++) acc[r] = make_float4(0.f, 0.f, 0.f, 0.f);
#pragma unroll 4
    for (int k = 0; k < K; k++) {
        float4 wv = __ldg(reinterpret_cast<const float4*>(W + k * HD) + j0);
#pragma unroll
        for (int r = 0; r < RPT; r++) {
            float xv = xs[sg * RPT + r][k];
            acc[r].x += xv * wv.x;
            acc[r].y += xv * wv.y;
            acc[r].z += xv * wv.z;
            acc[r].w += xv * wv.w;
        }
    }
#pragma unroll
    for (int r = 0; r < RPT; r++) {
        long long row = base + sg * RPT + r;
        if (row < n) {
            float dv = __ldg(&d_dinv[row]);
            reinterpret_cast<float4*>(d_h)[row * 16 + j0] =
                make_float4(acc[r].x * dv, acc[r].y * dv, acc[r].z * dv, acc[r].w * dv);
        }
    }
}

// GCN gather (CSR): h2[g] = h[g] + sum_{r in in(g)} h[r]   (no atomics)
__global__ void k_gcn_gather(int n) {
    int g = blockIdx.x * 16 + (threadIdx.x >> 4);
    int q = threadIdx.x & 15;
    if (g >= n) return;
    int o0 = d_off[g], o1 = d_off[g + 1];
    float4 acc = reinterpret_cast<const float4*>(d_h)[g * 16 + q];
    for (int o = o0; o < o1; o++) {
        int r = __ldg(&d_epack[o].x);
        float4 v = __ldg(reinterpret_cast<const float4*>(d_h) + r * 16 + q);
        acc.x += v.x; acc.y += v.y; acc.z += v.z; acc.w += v.w;
    }
    reinterpret_cast<float4*>(d_h2)[g * 16 + q] = acc;
}

// ---------------- GAT GEMM (R10 shape, fused relu(dinv*h2+b1)) ----------------
__global__ void k_gemm_gat(const float* __restrict__ Wg, const float* __restrict__ b1, int n) {
    const int K = HD, M = NHEADS * HD, JT = 64, SG = 4, RPT = 8;
    const int ROWS = SG * RPT;                       // 32
    __shared__ float xs[ROWS][K];
    int tid = threadIdx.x;
    int j0  = tid % JT;
    int sg  = tid / JT;
    long long base = (long long)blockIdx.x * ROWS;
    {
        const int T4 = ROWS * (K / 4);
        for (int i4 = tid; i4 < T4; i4 += 256) {
            long long row = base + i4 / (K / 4);
            int col4 = i4 % (K / 4);
            float4 v = make_float4(0.f, 0.f, 0.f, 0.f);
            if (row < n) {
                float4 h2v = __ldg(reinterpret_cast<const float4*>(d_h2) + row * 16 + col4);
                float4 bv  = __ldg(reinterpret_cast<const float4*>(b1) + col4);
                float dv = __ldg(&d_dinv[row]);
                v.x = fmaxf(dv * h2v.x + bv.x, 0.f);
                v.y = fmaxf(dv * h2v.y + bv.y, 0.f);
                v.z = fmaxf(dv * h2v.z + bv.z, 0.f);
                v.w = fmaxf(dv * h2v.w + bv.w, 0.f);
            }
            reinterpret_cast<float4*>(xs)[i4] = v;
        }
    }
    __syncthreads();
    float4 acc[RPT];
#pragma unroll
    for (int r = 0; r < RPT; r++) acc[r] = make_float4(0.f, 0.f, 0.f, 0.f);
#pragma unroll 4
    for (int k = 0; k < K; k++) {
        float4 wv = __ldg(reinterpret_cast<const float4*>(Wg + k * M) + j0);
#pragma unroll
        for (int r = 0; r < RPT; r++) {
            float xv = xs[sg * RPT + r][k];
            acc[r].x += xv * wv.x;
            acc[r].y += xv * wv.y;
            acc[r].z += xv * wv.z;
            acc[r].w += xv * wv.w;
        }
    }
#pragma unroll
    for (int r = 0; r < RPT; r++) {
        long long row = base + sg * RPT + r;
        if (row < n)
            reinterpret_cast<float4*>(d_hg)[row * 64 + j0] = acc[r];
    }
}

// per-(node,head) attention logits + denom init = exp(self logit)
__global__ void k_att(const float* __restrict__ att_src,
                      const float* __restrict__ att_dst, int n) {
    long long w = (long long)(blockIdx.x * blockDim.x + threadIdx.x) >> 5;
    int lane = threadIdx.x & 31;
    long long total = (long long)n * NHEADS;
    long long stride = ((long long)gridDim.x * blockDim.x) >> 5;
    for (; w < total; w += stride) {
        int node = (int)(w >> 2), head = (int)(w & 3);
        const float* hgp = &d_hg[(long long)node * (NHEADS * HD) + head * HD];
        float s = hgp[lane] * __ldg(&att_src[head * HD + lane]) +
                  hgp[lane + 32] * __ldg(&att_src[head * HD + lane + 32]);
        float t = hgp[lane] * __ldg(&att_dst[head * HD + lane]) +
                  hgp[lane + 32] * __ldg(&att_dst[head * HD + lane + 32]);
#pragma unroll
        for (int o = 16; o; o >>= 1) {
            s += __shfl_down_sync(0xffffffffu, s, o);
            t += __shfl_down_sync(0xffffffffu, t, o);
        }
        if (lane == 0) {
            d_asrc[w] = s;
            d_adst[w] = t;
            d_den[w]  = expf(lrelu(s + t));
        }
    }
}

// per-edge ex = exp(lrelu(asrc[r]+adst[c])): store + vector-RED into denom
__global__ void k_den_edges(int e) {
    int i = blockIdx.x * blockDim.x + threadIdx.x;
    if (i < e) {
        int r = d_row32[i], c = d_col32[i];
        const float4 as = reinterpret_cast<const float4*>(d_asrc)[r];
        const float4 ad = reinterpret_cast<const float4*>(d_adst)[c];
        float4 ex;
        ex.x = expf(lrelu(as.x + ad.x));
        ex.y = expf(lrelu(as.y + ad.y));
        ex.z = expf(lrelu(as.z + ad.z));
        ex.w = expf(lrelu(as.w + ad.w));
        reinterpret_cast<float4*>(d_alpha)[i] = ex;
        red_add_v4(&reinterpret_cast<float4*>(d_den)[c], ex);
    }
}

// GAT gather (CSR): hga[g] = sum over {self, in-edges} of per-head weighted hg rows
__global__ void k_gat_gather(int n) {
    int g = blockIdx.x * 16 + (threadIdx.x >> 4);
    int q = threadIdx.x & 15;
    if (g >= n) return;
    const float4 dn = reinterpret_cast<const float4*>(d_den)[g];
    float ix = 0.25f / dn.x, iy = 0.25f / dn.y, iz = 0.25f / dn.z, iw = 0.25f / dn.w;
    // self contribution
    const float4 as = reinterpret_cast<const float4*>(d_asrc)[g];
    const float4 ad = reinterpret_cast<const float4*>(d_adst)[g];
    float wx = expf(lrelu(as.x + ad.x)) * ix;
    float wy = expf(lrelu(as.y + ad.y)) * iy;
    float wz = expf(lrelu(as.z + ad.z)) * iz;
    float ww = expf(lrelu(as.w + ad.w)) * iw;
    const float4* hg4 = reinterpret_cast<const float4*>(d_hg);
    long long sbase = (long long)g * 64;
    float4 a = hg4[sbase + 0 * 16 + q];
    float4 b = hg4[sbase + 1 * 16 + q];
    float4 cc = hg4[sbase + 2 * 16 + q];
    float4 dd = hg4[sbase + 3 * 16 + q];
    float4 acc;
    acc.x = wx * a.x + wy * b.x + wz * cc.x + ww * dd.x;
    acc.y = wx * a.y + wy * b.y + wz * cc.y + ww * dd.y;
    acc.z = wx * a.z + wy * b.z + wz * cc.z + ww * dd.z;
    acc.w = wx * a.w + wy * b.w + wz * cc.w + ww * dd.w;
    int o0 = d_off[g], o1 = d_off[g + 1];
    for (int o = o0; o < o1; o++) {
        int2 pk = __ldg(&d_epack[o]);
        const float4 ex = __ldg(reinterpret_cast<const float4*>(d_alpha) + pk.y);
        float ex0 = ex.x * ix, ex1 = ex.y * iy, ex2 = ex.z * iz, ex3 = ex.w * iw;
        long long base = (long long)pk.x * 64;
        float4 ra = hg4[base + 0 * 16 + q];
        float4 rb = hg4[base + 1 * 16 + q];
        float4 rc = hg4[base + 2 * 16 + q];
        float4 rd = hg4[base + 3 * 16 + q];
        acc.x += ex0 * ra.x + ex1 * rb.x + ex2 * rc.x + ex3 * rd.x;
        acc.y += ex0 * ra.y + ex1 * rb.y + ex2 * rc.y + ex3 * rd.y;
        acc.z += ex0 * ra.z + ex1 * rb.z + ex2 * rc.z + ex3 * rd.z;
        acc.w += ex0 * ra.w + ex1 * rb.w + ex2 * rc.w + ex3 * rd.w;
    }
    reinterpret_cast<float4*>(d_hga)[g * 16 + q] = acc;
}

// SAGE gather (CSR): mean[g] = sum_{r in in(g)} relu(hga[r]+bg)  (divide in k_final)
__global__ void k_sage_gather(const float* __restrict__ bg, int n) {
    int g = blockIdx.x * 16 + (threadIdx.x >> 4);
    int q = threadIdx.x & 15;
    if (g >= n) return;
    float4 bv = __ldg(reinterpret_cast<const float4*>(bg) + q);
    float4 acc = make_float4(0.f, 0.f, 0.f, 0.f);
    int o0 = d_off[g], o1 = d_off[g + 1];
    for (int o = o0; o < o1; o++) {
        int r = __ldg(&d_epack[o].x);
        float4 h = __ldg(reinterpret_cast<const float4*>(d_hga) + r * 16 + q);
        acc.x += fmaxf(h.x + bv.x, 0.f);
        acc.y += fmaxf(h.y + bv.y, 0.f);
        acc.z += fmaxf(h.z + bv.z, 0.f);
        acc.w += fmaxf(h.w + bv.w, 0.f);
    }
    reinterpret_cast<float4*>(d_mean)[g * 16 + q] = acc;
}

// final: emb = (mean/deg)@Wl + bl + relu(hga+bg)@Wr ; MLP heads ; outputs
__global__ void k_final(const float* __restrict__ Wl, const float* __restrict__ bl,
                        const float* __restrict__ Wr, const float* __restrict__ bg,
                        const float* __restrict__ a1w, const float* __restrict__ a1b,
                        const float* __restrict__ a2w, const float* __restrict__ a2b,
                        const float* __restrict__ r1w, const float* __restrict__ r1b,
                        const float* __restrict__ r2w, const float* __restrict__ r2b,
                        float* __restrict__ out_emb, float* __restrict__ out_an,
                        float* __restrict__ out_risk, int n) {
    __shared__ float Wls[HD * HD], Wrs[HD * HD];
    __shared__ float ms[4][HD], hs[4][HD], embs[4][HD];
    int tid = threadIdx.x;
    for (int i = tid; i < HD * HD; i += blockDim.x) {
        Wls[i] = Wl[i];
        Wrs[i] = Wr[i];
    }
    int sub = tid >> 6, j = tid & 63;
    int lane = tid & 31, wp = tid >> 5;
    int nd = wp >> 1, hd = wp & 1;
    for (long long base = (long long)blockIdx.x * 4; base < n;
         base += (long long)gridDim.x * 4) {
        int node = (int)base + sub;
        __syncthreads();
        if (node < n) {
            float inv = 1.f / fmaxf((float)d_deg[node], 1.f);
            ms[sub][j] = d_mean[node * HD + j] * inv;
            hs[sub][j] = fmaxf(d_hga[node * HD + j] + bg[j], 0.f);
        }
        __syncthreads();
        if (node < n) {
            float acc = bl[j];
#pragma unroll 16
            for (int k = 0; k < HD; k++)
                acc += ms[sub][k] * Wls[k * HD + j] + hs[sub][k] * Wrs[k * HD + j];
            embs[sub][j] = acc;
            out_emb[(long long)node * HD + j] = acc;
        }
        __syncthreads();
        int node2 = (int)base + nd;
        if (node2 < n) {
            const float* W1p = hd ? r1w : a1w;
            float acc = hd ? __ldg(&r1b[lane]) : __ldg(&a1b[lane]);
#pragma unroll 16
            for (int k = 0; k < HD; k++)
                acc += embs[nd][k] * __ldg(&W1p[k * 32 + lane]);
            acc = fmaxf(acc, 0.f) * (hd ? __ldg(&r2w[lane]) : __ldg(&a2w[lane]));
#pragma unroll
            for (int o = 16; o; o >>= 1) acc += __shfl_down_sync(0xffffffffu, acc, o);
            if (lane == 0) {
                float b2 = hd ? __ldg(&r2b[0]) : __ldg(&a2b[0]);
                float v = 1.f / (1.f + expf(-(acc + b2)));
                if (hd) out_risk[node2] = v;
                else    out_an[node2] = v;
            }
        }
    }
}

// ---------------- launcher ----------------
extern "C" void kernel_launch(void* const* d_in, const int* in_sizes, int n_in,
                              void* d_out, int out_size) {
    const float* x   = (const float*)d_in[0];
    const int*   ei  = (const int*)d_in[1];   // int32 (JAX x64 disabled)
    const float* W1  = (const float*)d_in[2];
    const float* b1  = (const float*)d_in[3];
    const float* Wg  = (const float*)d_in[4];
    const float* ats = (const float*)d_in[5];
    const float* atd = (const float*)d_in[6];
    const float* bg  = (const float*)d_in[7];
    const float* Wl  = (const float*)d_in[8];
    const float* bl  = (const float*)d_in[9];
    const float* Wr  = (const float*)d_in[10];
    const float* a1w = (const float*)d_in[11];
    const float* a1b = (const float*)d_in[12];
    const float* a2w = (const float*)d_in[13];
    const float* a2b = (const float*)d_in[14];
    const float* r1w = (const float*)d_in[15];
    const float* r1b = (const float*)d_in[16];
    const float* r2w = (const float*)d_in[17];
    const float* r2b = (const float*)d_in[18];

    int n = in_sizes[0] / FIN;
    int e = in_sizes[1] / 2;
    const int* row0 = ei;
    const int* col0 = ei + e;

    float* out      = (float*)d_out;
    float* out_emb  = out;
    float* out_an   = out + (long long)n * HD;
    float* out_risk = out_an + n;

    const int B = 256;
    int gN  = (n + B - 1) / B;
    int gE  = (e + B - 1) / B;
    int gG  = (n + 15) / 16;   // gather grids: 16 nodes/block

    // CSR build
    k_zero0<<<gN, B>>>(n);
    k_edges32<<<gE, B>>>(row0, col0, e, n);
    k_scan<<<1, 1024>>>(n);
    k_fill<<<gE, B>>>(e);
    k_dinv<<<gN, B>>>(n);

    // GCN
    k_gemm_gcn<<<(n + 63) / 64, 256>>>(x, W1, n);
    k_gcn_gather<<<gG, B>>>(n);

    // GAT
    k_gemm_gat<<<(n + 31) / 32, 256>>>(Wg, b1, n);
    k_att<<<(n * NHEADS * 32 + B - 1) / B, B>>>(ats, atd, n);
    k_den_edges<<<gE, B>>>(e);
    k_gat_gather<<<gG, B>>>(n);

    // SAGE
    k_sage_gather<<<gG, B>>>(bg, n);

    // emb + heads
    k_final<<<(n + 3) / 4, B>>>(Wl, bl, Wr, bg, a1w, a1b, a2w, a2b,
                                r1w, r1b, r2w, r2b,
                                out_emb, out_an, out_risk, n);
}